// round 15
// baseline (speedup 1.0000x reference)
#include <cuda_runtime.h>
#include <cuda_bf16.h>
#include <cstdint>
#include <cstddef>

// Problem constants
#define BATCH 8
#define SEQ   512
#define NTOK  4096      // BATCH*SEQ
#define EMB   1024
#define E3    3072
#define NHEAD 16
#define HDIM  64
#define HID   4096
#define ODIM  128
#define NLAYER 8

// ---------------------------------------------------------------------------
// Scratch (device globals; allocation is forbidden)
// ---------------------------------------------------------------------------
__device__ float g_z   [(size_t)NTOK * EMB];   // 16 MB
__device__ float g_qkv [(size_t)NTOK * E3];    // 48 MB
__device__ float g_attn[(size_t)NTOK * EMB];   // 16 MB
__device__ float g_tmp [(size_t)NTOK * EMB];   // 16 MB
__device__ float g_hid [(size_t)NTOK * HID];   // 64 MB
__device__ float g_M   [ODIM * ODIM];
__device__ float g_aug [ODIM * 2 * ODIM];
__device__ float g_P   [ODIM * EMB];

// ---------------------------------------------------------------------------
// helpers
// ---------------------------------------------------------------------------
__device__ __forceinline__ void ldmatrix4(uint32_t addr, uint32_t& r0, uint32_t& r1,
                                          uint32_t& r2, uint32_t& r3)
{
    asm volatile("ldmatrix.sync.aligned.m8n8.x4.shared.b16 {%0,%1,%2,%3}, [%4];"
                 : "=r"(r0), "=r"(r1), "=r"(r2), "=r"(r3) : "r"(addr));
}

__device__ __forceinline__ void mma16816(float* c, uint32_t a0, uint32_t a1,
                                         uint32_t a2, uint32_t a3,
                                         uint32_t b0, uint32_t b1)
{
    asm volatile("mma.sync.aligned.m16n8k16.row.col.f32.bf16.bf16.f32 "
                 "{%0,%1,%2,%3},{%4,%5,%6,%7},{%8,%9},{%0,%1,%2,%3};"
                 : "+f"(c[0]), "+f"(c[1]), "+f"(c[2]), "+f"(c[3])
                 : "r"(a0), "r"(a1), "r"(a2), "r"(a3), "r"(b0), "r"(b1));
}

__device__ __forceinline__ void split2(float x, float y, uint32_t& h, uint32_t& l)
{
    __nv_bfloat162 hv = __floats2bfloat162_rn(x, y);
    float rx = x - __bfloat162float(hv.x);
    float ry = y - __bfloat162float(hv.y);
    __nv_bfloat162 lv = __floats2bfloat162_rn(rx, ry);
    h = *reinterpret_cast<uint32_t*>(&hv);
    l = *reinterpret_cast<uint32_t*>(&lv);
}

// ===========================================================================
// Tensor-core GEMM 128x128 (champion, verbatim): used for FFN1
// ===========================================================================
#define TBM 128
#define TBN 128
#define TBK 32
#define RW  20
#define PLANE (128 * RW)
#define BUFW  (4 * PLANE)
#define TC_SMEM (2 * BUFW * 4)

__global__ void __launch_bounds__(256, 1) gemm_tc_kernel(
    const float* __restrict__ A, const float* __restrict__ B,
    const float* __restrict__ bias, float* __restrict__ C,
    int M, int N, int K, int op)   // op: 0=none, 1=bias, 2=bias+relu
{
    extern __shared__ uint32_t sm[];
    const uint32_t sbase = (uint32_t)__cvta_generic_to_shared(sm);

    const int tid = threadIdx.x;
    const int lane = tid & 31;
    const int wid = tid >> 5;
    const int wm = wid >> 2;
    const int wn = wid & 3;
    const int bm = blockIdx.y * TBM;
    const int bn = blockIdx.x * TBN;

    float acc[4][4][4];
#pragma unroll
    for (int i = 0; i < 4; i++)
#pragma unroll
        for (int j = 0; j < 4; j++)
#pragma unroll
            for (int r = 0; r < 4; r++) acc[i][j][r] = 0.f;

    int rows[4], c4s[4];
#pragma unroll
    for (int i = 0; i < 4; i++) {
        int f = tid + i * 256;
        rows[i] = f >> 3;
        c4s[i] = (f & 7) << 2;
    }

    const float* Ab = A + (size_t)bm * K;
    const float* Bb = B + (size_t)bn * K;

    float4 ra[4], rb[4];

#pragma unroll
    for (int i = 0; i < 4; i++) {
        ra[i] = *(const float4*)(Ab + (size_t)rows[i] * K + c4s[i]);
        rb[i] = *(const float4*)(Bb + (size_t)rows[i] * K + c4s[i]);
    }
    {
        uint32_t* buf = sm;
#pragma unroll
        for (int i = 0; i < 4; i++) {
            uint32_t h0, h1, l0, l1;
            int off = rows[i] * RW + (c4s[i] >> 1);
            split2(ra[i].x, ra[i].y, h0, l0);
            split2(ra[i].z, ra[i].w, h1, l1);
            buf[0 * PLANE + off] = h0; buf[0 * PLANE + off + 1] = h1;
            buf[1 * PLANE + off] = l0; buf[1 * PLANE + off + 1] = l1;
            split2(rb[i].x, rb[i].y, h0, l0);
            split2(rb[i].z, rb[i].w, h1, l1);
            buf[2 * PLANE + off] = h0; buf[2 * PLANE + off + 1] = h1;
            buf[3 * PLANE + off] = l0; buf[3 * PLANE + off + 1] = l1;
        }
    }
    __syncthreads();

    const int arow = wm * 64 + (lane & 7) + ((lane & 8) ? 8 : 0);
    const int akw0 = (lane & 16) ? 4 : 0;
    const int brow = wn * 32 + (lane & 7) + ((lane & 16) ? 8 : 0);
    const int bkw0 = (lane & 8) ? 4 : 0;

    const int T = K / TBK;
    for (int t = 0; t < T; t++) {
        if (t + 1 < T) {
            const int k0 = (t + 1) * TBK;
#pragma unroll
            for (int i = 0; i < 4; i++) {
                ra[i] = *(const float4*)(Ab + (size_t)rows[i] * K + k0 + c4s[i]);
                rb[i] = *(const float4*)(Bb + (size_t)rows[i] * K + k0 + c4s[i]);
            }
        }

        const uint32_t bufb = sbase + (uint32_t)((t & 1) * BUFW) * 4u;
#pragma unroll
        for (int ks = 0; ks < 2; ks++) {
            uint32_t ah[4][4], al[4][4], bh[4][2], bl[4][2];
            const int akw = ks * 8 + akw0;
            const int bkw = ks * 8 + bkw0;
#pragma unroll
            for (int mt = 0; mt < 4; mt++) {
                ldmatrix4(bufb + 4u * (0 * PLANE + (arow + mt * 16) * RW + akw),
                          ah[mt][0], ah[mt][1], ah[mt][2], ah[mt][3]);
                ldmatrix4(bufb + 4u * (1 * PLANE + (arow + mt * 16) * RW + akw),
                          al[mt][0], al[mt][1], al[mt][2], al[mt][3]);
            }
#pragma unroll
            for (int np = 0; np < 2; np++) {
                uint32_t r0, r1, r2, r3;
                ldmatrix4(bufb + 4u * (2 * PLANE + (brow + np * 16) * RW + bkw),
                          r0, r1, r2, r3);
                bh[2 * np][0] = r0; bh[2 * np][1] = r1;
                bh[2 * np + 1][0] = r2; bh[2 * np + 1][1] = r3;
                ldmatrix4(bufb + 4u * (3 * PLANE + (brow + np * 16) * RW + bkw),
                          r0, r1, r2, r3);
                bl[2 * np][0] = r0; bl[2 * np][1] = r1;
                bl[2 * np + 1][0] = r2; bl[2 * np + 1][1] = r3;
            }
#pragma unroll
            for (int mt = 0; mt < 4; mt++)
#pragma unroll
                for (int nt = 0; nt < 4; nt++) {
                    float* c = acc[mt][nt];
                    mma16816(c, ah[mt][0], ah[mt][1], ah[mt][2], ah[mt][3],
                             bh[nt][0], bh[nt][1]);
                    mma16816(c, ah[mt][0], ah[mt][1], ah[mt][2], ah[mt][3],
                             bl[nt][0], bl[nt][1]);
                    mma16816(c, al[mt][0], al[mt][1], al[mt][2], al[mt][3],
                             bh[nt][0], bh[nt][1]);
                }
        }
        __syncthreads();

        if (t + 1 < T) {
            uint32_t* buf = sm + ((t + 1) & 1) * BUFW;
#pragma unroll
            for (int i = 0; i < 4; i++) {
                uint32_t h0, h1, l0, l1;
                int off = rows[i] * RW + (c4s[i] >> 1);
                split2(ra[i].x, ra[i].y, h0, l0);
                split2(ra[i].z, ra[i].w, h1, l1);
                buf[0 * PLANE + off] = h0; buf[0 * PLANE + off + 1] = h1;
                buf[1 * PLANE + off] = l0; buf[1 * PLANE + off + 1] = l1;
                split2(rb[i].x, rb[i].y, h0, l0);
                split2(rb[i].z, rb[i].w, h1, l1);
                buf[2 * PLANE + off] = h0; buf[2 * PLANE + off + 1] = h1;
                buf[3 * PLANE + off] = l0; buf[3 * PLANE + off + 1] = l1;
            }
        }
        __syncthreads();
    }

#pragma unroll
    for (int mt = 0; mt < 4; mt++) {
        const int row = bm + wm * 64 + mt * 16 + (lane >> 2);
#pragma unroll
        for (int nt = 0; nt < 4; nt++) {
            const int col = bn + wn * 32 + nt * 8 + 2 * (lane & 3);
            float b0 = 0.f, b1 = 0.f;
            if (op >= 1) { b0 = bias[col]; b1 = bias[col + 1]; }
            float v0 = acc[mt][nt][0] + b0;
            float v1 = acc[mt][nt][1] + b1;
            float v2 = acc[mt][nt][2] + b0;
            float v3 = acc[mt][nt][3] + b1;
            if (op == 2) {
                v0 = fmaxf(v0, 0.f); v1 = fmaxf(v1, 0.f);
                v2 = fmaxf(v2, 0.f); v3 = fmaxf(v3, 0.f);
            }
            *(float2*)(C + (size_t)row * N + col) = make_float2(v0, v1);
            *(float2*)(C + (size_t)(row + 8) * N + col) = make_float2(v2, v3);
        }
    }
}

// ===========================================================================
// Tensor-core GEMM 64x64, TBK=64, occ 2: used for QKV / proj / FFN2 / readout
// (same split-bf16 recipe; finer grid kills wave quantization)
// ===========================================================================
#define RW6 36                   // 32 data words (64 bf16) + 4 pad
#define PL6 (64 * RW6)           // 2304 words
#define BW6 (4 * PL6)            // 9216 words = 36 KB
#define TC6_SMEM (2 * BW6 * 4)   // 73728 B

__global__ void __launch_bounds__(256, 2) gemm_tc64_kernel(
    const float* __restrict__ A, const float* __restrict__ B,
    const float* __restrict__ bias, float* __restrict__ C,
    int M, int N, int K, int op)
{
    extern __shared__ uint32_t sm[];
    const uint32_t sbase = (uint32_t)__cvta_generic_to_shared(sm);

    const int tid = threadIdx.x;
    const int lane = tid & 31;
    const int wid = tid >> 5;
    const int wm = wid >> 2;      // 0..1 (32-row slab)
    const int wn = wid & 3;       // 0..3 (16-col slab)
    const int bm = blockIdx.y * 64;
    const int bn = blockIdx.x * 64;

    float acc[2][2][4];
#pragma unroll
    for (int i = 0; i < 2; i++)
#pragma unroll
        for (int j = 0; j < 2; j++)
#pragma unroll
            for (int r = 0; r < 4; r++) acc[i][j][r] = 0.f;

    // staging: 64 rows x 16 float4 per matrix = 1024 float4 -> 4/thread each
    int rows[4], c4s[4];
#pragma unroll
    for (int i = 0; i < 4; i++) {
        int f = tid + i * 256;
        rows[i] = f >> 4;              // 0..63
        c4s[i] = (f & 15) << 2;        // 0,4,...,60
    }

    const float* Ab = A + (size_t)bm * K;
    const float* Bb = B + (size_t)bn * K;

    float4 ra[4], rb[4];

#pragma unroll
    for (int i = 0; i < 4; i++) {
        ra[i] = *(const float4*)(Ab + (size_t)rows[i] * K + c4s[i]);
        rb[i] = *(const float4*)(Bb + (size_t)rows[i] * K + c4s[i]);
    }
    {
        uint32_t* buf = sm;
#pragma unroll
        for (int i = 0; i < 4; i++) {
            uint32_t h0, h1, l0, l1;
            int off = rows[i] * RW6 + (c4s[i] >> 1);
            split2(ra[i].x, ra[i].y, h0, l0);
            split2(ra[i].z, ra[i].w, h1, l1);
            buf[0 * PL6 + off] = h0; buf[0 * PL6 + off + 1] = h1;
            buf[1 * PL6 + off] = l0; buf[1 * PL6 + off + 1] = l1;
            split2(rb[i].x, rb[i].y, h0, l0);
            split2(rb[i].z, rb[i].w, h1, l1);
            buf[2 * PL6 + off] = h0; buf[2 * PL6 + off + 1] = h1;
            buf[3 * PL6 + off] = l0; buf[3 * PL6 + off + 1] = l1;
        }
    }
    __syncthreads();

    const int arow = wm * 32 + (lane & 7) + ((lane & 8) ? 8 : 0);
    const int akw0 = (lane & 16) ? 4 : 0;
    const int brow = wn * 16 + (lane & 7) + ((lane & 16) ? 8 : 0);
    const int bkw0 = (lane & 8) ? 4 : 0;

    const int T = K / 64;
    for (int t = 0; t < T; t++) {
        if (t + 1 < T) {
            const int k0 = (t + 1) * 64;
#pragma unroll
            for (int i = 0; i < 4; i++) {
                ra[i] = *(const float4*)(Ab + (size_t)rows[i] * K + k0 + c4s[i]);
                rb[i] = *(const float4*)(Bb + (size_t)rows[i] * K + k0 + c4s[i]);
            }
        }

        const uint32_t bufb = sbase + (uint32_t)((t & 1) * BW6) * 4u;
#pragma unroll
        for (int ks = 0; ks < 4; ks++) {
            const int akw = ks * 8 + akw0;
            const int bkw = ks * 8 + bkw0;
            uint32_t ah[2][4], al[2][4], bh[2][2], bl[2][2];
#pragma unroll
            for (int mt = 0; mt < 2; mt++) {
                ldmatrix4(bufb + 4u * (0 * PL6 + (arow + mt * 16) * RW6 + akw),
                          ah[mt][0], ah[mt][1], ah[mt][2], ah[mt][3]);
                ldmatrix4(bufb + 4u * (1 * PL6 + (arow + mt * 16) * RW6 + akw),
                          al[mt][0], al[mt][1], al[mt][2], al[mt][3]);
            }
            {
                uint32_t r0, r1, r2, r3;
                ldmatrix4(bufb + 4u * (2 * PL6 + brow * RW6 + bkw), r0, r1, r2, r3);
                bh[0][0] = r0; bh[0][1] = r1; bh[1][0] = r2; bh[1][1] = r3;
                ldmatrix4(bufb + 4u * (3 * PL6 + brow * RW6 + bkw), r0, r1, r2, r3);
                bl[0][0] = r0; bl[0][1] = r1; bl[1][0] = r2; bl[1][1] = r3;
            }
#pragma unroll
            for (int mt = 0; mt < 2; mt++)
#pragma unroll
                for (int nt = 0; nt < 2; nt++) {
                    float* c = acc[mt][nt];
                    mma16816(c, ah[mt][0], ah[mt][1], ah[mt][2], ah[mt][3],
                             bh[nt][0], bh[nt][1]);
                    mma16816(c, ah[mt][0], ah[mt][1], ah[mt][2], ah[mt][3],
                             bl[nt][0], bl[nt][1]);
                    mma16816(c, al[mt][0], al[mt][1], al[mt][2], al[mt][3],
                             bh[nt][0], bh[nt][1]);
                }
        }
        __syncthreads();

        if (t + 1 < T) {
            uint32_t* buf = sm + ((t + 1) & 1) * BW6;
#pragma unroll
            for (int i = 0; i < 4; i++) {
                uint32_t h0, h1, l0, l1;
                int off = rows[i] * RW6 + (c4s[i] >> 1);
                split2(ra[i].x, ra[i].y, h0, l0);
                split2(ra[i].z, ra[i].w, h1, l1);
                buf[0 * PL6 + off] = h0; buf[0 * PL6 + off + 1] = h1;
                buf[1 * PL6 + off] = l0; buf[1 * PL6 + off + 1] = l1;
                split2(rb[i].x, rb[i].y, h0, l0);
                split2(rb[i].z, rb[i].w, h1, l1);
                buf[2 * PL6 + off] = h0; buf[2 * PL6 + off + 1] = h1;
                buf[3 * PL6 + off] = l0; buf[3 * PL6 + off + 1] = l1;
            }
        }
        __syncthreads();
    }

#pragma unroll
    for (int mt = 0; mt < 2; mt++) {
        const int row = bm + wm * 32 + mt * 16 + (lane >> 2);
#pragma unroll
        for (int nt = 0; nt < 2; nt++) {
            const int col = bn + wn * 16 + nt * 8 + 2 * (lane & 3);
            float b0 = 0.f, b1 = 0.f;
            if (op >= 1) { b0 = bias[col]; b1 = bias[col + 1]; }
            float v0 = acc[mt][nt][0] + b0;
            float v1 = acc[mt][nt][1] + b1;
            float v2 = acc[mt][nt][2] + b0;
            float v3 = acc[mt][nt][3] + b1;
            if (op == 2) {
                v0 = fmaxf(v0, 0.f); v1 = fmaxf(v1, 0.f);
                v2 = fmaxf(v2, 0.f); v3 = fmaxf(v3, 0.f);
            }
            *(float2*)(C + (size_t)row * N + col) = make_float2(v0, v1);
            *(float2*)(C + (size_t)(row + 8) * N + col) = make_float2(v2, v3);
        }
    }
}

// ===========================================================================
// Tensor-core flash attention (round-14 champion, verbatim)
// ===========================================================================
#define RWQ 36
#define RWP 68
#define AQH 0
#define AQL 4608
#define AKH 9216
#define AKL 13824
#define AVH 18432
#define AVL 22784
#define APH 27136
#define APL 35840
#define AWMAX 44544
#define AWSUM 45056
#define ATT_SMEM (45568 * 4)

__global__ void __launch_bounds__(256, 1) attn_mma_kernel(
    const float* __restrict__ qkv, float* __restrict__ out)
{
    extern __shared__ uint32_t sm[];
    const uint32_t sbase = (uint32_t)__cvta_generic_to_shared(sm);
    __nv_bfloat16* smh = (__nv_bfloat16*)sm;

    const int tid = threadIdx.x;
    const int lane = tid & 31;
    const int wid = tid >> 5;
    const int wm = wid >> 2, wn = wid & 3;
    const int qg = blockIdx.x;
    const int b = blockIdx.y >> 4, h = blockIdx.y & 15;

    const float* base = qkv + (size_t)(b * SEQ) * E3 + h * (3 * HDIM);

#pragma unroll
    for (int i = 0; i < 8; i++) {
        int f = tid + i * 256;
        int row = f >> 4, c4 = (f & 15) << 2;
        float4 v = *(const float4*)(base + (size_t)(qg * 128 + row) * E3 + c4);
        uint32_t h0, l0, h1, l1;
        split2(v.x, v.y, h0, l0);
        split2(v.z, v.w, h1, l1);
        int off = row * RWQ + (c4 >> 1);
        sm[AQH + off] = h0; sm[AQH + off + 1] = h1;
        sm[AQL + off] = l0; sm[AQL + off + 1] = l1;
    }

    float accO[4][2][4];
    float m_reg[4][2], l_reg[4][2];
#pragma unroll
    for (int mt = 0; mt < 4; mt++) {
#pragma unroll
        for (int n2 = 0; n2 < 2; n2++)
#pragma unroll
            for (int r = 0; r < 4; r++) accO[mt][n2][r] = 0.f;
        m_reg[mt][0] = -1e30f; m_reg[mt][1] = -1e30f;
        l_reg[mt][0] = 0.f;    l_reg[mt][1] = 0.f;
    }

    const int arow = wm * 64 + (lane & 7) + ((lane & 8) ? 8 : 0);
    const int akw0 = (lane & 16) ? 4 : 0;
    const int brow = wn * 32 + (lane & 7) + ((lane & 16) ? 8 : 0);
    const int bkw0 = (lane & 8) ? 4 : 0;
    const int brow2 = wn * 16 + (lane & 7) + ((lane & 16) ? 8 : 0);
    const int rbase0 = wm * 64 + (lane >> 2);

    float* wmaxf = (float*)&sm[AWMAX];
    float* wsumf = (float*)&sm[AWSUM];

    for (int c = 0; c < 4; c++) {
        __syncthreads();

#pragma unroll
        for (int i = 0; i < 8; i++) {
            int f = tid + i * 256;
            int row = f >> 4, c4 = (f & 15) << 2;
            float4 v = *(const float4*)(base + (size_t)(c * 128 + row) * E3 + HDIM + c4);
            uint32_t h0, l0, h1, l1;
            split2(v.x, v.y, h0, l0);
            split2(v.z, v.w, h1, l1);
            int off = row * RWQ + (c4 >> 1);
            sm[AKH + off] = h0; sm[AKH + off + 1] = h1;
            sm[AKL + off] = l0; sm[AKL + off + 1] = l1;
        }
#pragma unroll
        for (int i = 0; i < 8; i++) {
            int f = tid + i * 256;
            int r = f >> 4, d4 = (f & 15) << 2;
            float4 v = *(const float4*)(base + (size_t)(c * 128 + r) * E3 + 2 * HDIM + d4);
            float vv[4] = {v.x, v.y, v.z, v.w};
#pragma unroll
            for (int j = 0; j < 4; j++) {
                __nv_bfloat16 hb = __float2bfloat16_rn(vv[j]);
                __nv_bfloat16 lb = __float2bfloat16_rn(vv[j] - __bfloat162float(hb));
                smh[(AVH + (d4 + j) * RWP) * 2 + r] = hb;
                smh[(AVL + (d4 + j) * RWP) * 2 + r] = lb;
            }
        }
        __syncthreads();

        float accS[4][4][4];
#pragma unroll
        for (int i = 0; i < 4; i++)
#pragma unroll
            for (int j = 0; j < 4; j++)
#pragma unroll
                for (int r = 0; r < 4; r++) accS[i][j][r] = 0.f;

#pragma unroll
        for (int kt = 0; kt < 2; kt++)
#pragma unroll
            for (int ks = 0; ks < 2; ks++) {
                const int akw = kt * 16 + ks * 8 + akw0;
                const int bkw = kt * 16 + ks * 8 + bkw0;
                uint32_t qh[4][4], ql[4][4], kh[4][2], kl[4][2];
#pragma unroll
                for (int mt = 0; mt < 4; mt++) {
                    ldmatrix4(sbase + 4u * (AQH + (arow + mt * 16) * RWQ + akw),
                              qh[mt][0], qh[mt][1], qh[mt][2], qh[mt][3]);
                    ldmatrix4(sbase + 4u * (AQL + (arow + mt * 16) * RWQ + akw),
                              ql[mt][0], ql[mt][1], ql[mt][2], ql[mt][3]);
                }
#pragma unroll
                for (int np = 0; np < 2; np++) {
                    uint32_t r0, r1, r2, r3;
                    ldmatrix4(sbase + 4u * (AKH + (brow + np * 16) * RWQ + bkw),
                              r0, r1, r2, r3);
                    kh[2 * np][0] = r0; kh[2 * np][1] = r1;
                    kh[2 * np + 1][0] = r2; kh[2 * np + 1][1] = r3;
                    ldmatrix4(sbase + 4u * (AKL + (brow + np * 16) * RWQ + bkw),
                              r0, r1, r2, r3);
                    kl[2 * np][0] = r0; kl[2 * np][1] = r1;
                    kl[2 * np + 1][0] = r2; kl[2 * np + 1][1] = r3;
                }
#pragma unroll
                for (int mt = 0; mt < 4; mt++)
#pragma unroll
                    for (int nt = 0; nt < 4; nt++) {
                        float* cc = accS[mt][nt];
                        mma16816(cc, qh[mt][0], qh[mt][1], qh[mt][2], qh[mt][3],
                                 kh[nt][0], kh[nt][1]);
                        mma16816(cc, qh[mt][0], qh[mt][1], qh[mt][2], qh[mt][3],
                                 kl[nt][0], kl[nt][1]);
                        mma16816(cc, ql[mt][0], ql[mt][1], ql[mt][2], ql[mt][3],
                                 kh[nt][0], kh[nt][1]);
                    }
            }

#pragma unroll
        for (int mt = 0; mt < 4; mt++) {
            float x0 = accS[mt][0][0], x1 = accS[mt][0][2];
#pragma unroll
            for (int nt = 0; nt < 4; nt++) {
                x0 = fmaxf(x0, fmaxf(accS[mt][nt][0], accS[mt][nt][1]));
                x1 = fmaxf(x1, fmaxf(accS[mt][nt][2], accS[mt][nt][3]));
            }
            x0 = fmaxf(x0, __shfl_xor_sync(0xffffffffu, x0, 1));
            x0 = fmaxf(x0, __shfl_xor_sync(0xffffffffu, x0, 2));
            x1 = fmaxf(x1, __shfl_xor_sync(0xffffffffu, x1, 1));
            x1 = fmaxf(x1, __shfl_xor_sync(0xffffffffu, x1, 2));
            if ((lane & 3) == 0) {
                wmaxf[wn * 128 + rbase0 + mt * 16] = x0;
                wmaxf[wn * 128 + rbase0 + mt * 16 + 8] = x1;
            }
        }
        __syncthreads();

        float alpha[4][2], psum[4][2];
#pragma unroll
        for (int mt = 0; mt < 4; mt++)
#pragma unroll
            for (int j = 0; j < 2; j++) {
                int row = rbase0 + mt * 16 + j * 8;
                float mc = fmaxf(fmaxf(wmaxf[row], wmaxf[128 + row]),
                                 fmaxf(wmaxf[256 + row], wmaxf[384 + row])) * 0.125f;
                float mn = fmaxf(m_reg[mt][j], mc);
                alpha[mt][j] = __expf(m_reg[mt][j] - mn);
                m_reg[mt][j] = mn;
                psum[mt][j] = 0.f;
            }
#pragma unroll
        for (int mt = 0; mt < 4; mt++) {
            const int row = rbase0 + mt * 16;
#pragma unroll
            for (int nt = 0; nt < 4; nt++) {
                const int col = wn * 32 + nt * 8 + 2 * (lane & 3);
                float p0 = __expf(accS[mt][nt][0] * 0.125f - m_reg[mt][0]);
                float p1 = __expf(accS[mt][nt][1] * 0.125f - m_reg[mt][0]);
                float p2 = __expf(accS[mt][nt][2] * 0.125f - m_reg[mt][1]);
                float p3 = __expf(accS[mt][nt][3] * 0.125f - m_reg[mt][1]);
                psum[mt][0] += p0 + p1;
                psum[mt][1] += p2 + p3;
                uint32_t hh, ll;
                split2(p0, p1, hh, ll);
                sm[APH + row * RWP + (col >> 1)] = hh;
                sm[APL + row * RWP + (col >> 1)] = ll;
                split2(p2, p3, hh, ll);
                sm[APH + (row + 8) * RWP + (col >> 1)] = hh;
                sm[APL + (row + 8) * RWP + (col >> 1)] = ll;
            }
        }
#pragma unroll
        for (int mt = 0; mt < 4; mt++)
#pragma unroll
            for (int j = 0; j < 2; j++) {
                float s = psum[mt][j];
                s += __shfl_xor_sync(0xffffffffu, s, 1);
                s += __shfl_xor_sync(0xffffffffu, s, 2);
                psum[mt][j] = s;
            }
        if ((lane & 3) == 0)
#pragma unroll
            for (int mt = 0; mt < 4; mt++) {
                wsumf[wn * 128 + rbase0 + mt * 16] = psum[mt][0];
                wsumf[wn * 128 + rbase0 + mt * 16 + 8] = psum[mt][1];
            }
#pragma unroll
        for (int mt = 0; mt < 4; mt++)
#pragma unroll
            for (int n2 = 0; n2 < 2; n2++) {
                accO[mt][n2][0] *= alpha[mt][0];
                accO[mt][n2][1] *= alpha[mt][0];
                accO[mt][n2][2] *= alpha[mt][1];
                accO[mt][n2][3] *= alpha[mt][1];
            }
        __syncthreads();

#pragma unroll
        for (int mt = 0; mt < 4; mt++)
#pragma unroll
            for (int j = 0; j < 2; j++) {
                int row = rbase0 + mt * 16 + j * 8;
                float s = wsumf[row] + wsumf[128 + row] + wsumf[256 + row] + wsumf[384 + row];
                l_reg[mt][j] = l_reg[mt][j] * alpha[mt][j] + s;
            }

#pragma unroll
        for (int kt = 0; kt < 4; kt++)
#pragma unroll
            for (int ks = 0; ks < 2; ks++) {
                const int akw = kt * 16 + ks * 8 + akw0;
                const int bkw = kt * 16 + ks * 8 + bkw0;
                uint32_t ph[4][4], pl[4][4], vh[2][2], vl[2][2];
#pragma unroll
                for (int mt = 0; mt < 4; mt++) {
                    ldmatrix4(sbase + 4u * (APH + (arow + mt * 16) * RWP + akw),
                              ph[mt][0], ph[mt][1], ph[mt][2], ph[mt][3]);
                    ldmatrix4(sbase + 4u * (APL + (arow + mt * 16) * RWP + akw),
                              pl[mt][0], pl[mt][1], pl[mt][2], pl[mt][3]);
                }
                {
                    uint32_t r0, r1, r2, r3;
                    ldmatrix4(sbase + 4u * (AVH + brow2 * RWP + bkw), r0, r1, r2, r3);
                    vh[0][0] = r0; vh[0][1] = r1; vh[1][0] = r2; vh[1][1] = r3;
                    ldmatrix4(sbase + 4u * (AVL + brow2 * RWP + bkw), r0, r1, r2, r3);
                    vl[0][0] = r0; vl[0][1] = r1; vl[1][0] = r2; vl[1][1] = r3;
                }
#pragma unroll
                for (int mt = 0; mt < 4; mt++)
#pragma unroll
                    for (int n2 = 0; n2 < 2; n2++) {
                        float* cc = accO[mt][n2];
                        mma16816(cc, ph[mt][0], ph[mt][1], ph[mt][2], ph[mt][3],
                                 vh[n2][0], vh[n2][1]);
                        mma16816(cc, ph[mt][0], ph[mt][1], ph[mt][2], ph[mt][3],
                                 vl[n2][0], vl[n2][1]);
                        mma16816(cc, pl[mt][0], pl[mt][1], pl[mt][2], pl[mt][3],
                                 vh[n2][0], vh[n2][1]);
                    }
            }
    }

#pragma unroll
    for (int mt = 0; mt < 4; mt++) {
        const int row = rbase0 + mt * 16;
        const int t0 = b * SEQ + qg * 128 + row;
        const float inv0 = 1.f / l_reg[mt][0];
        const float inv1 = 1.f / l_reg[mt][1];
#pragma unroll
        for (int n2 = 0; n2 < 2; n2++) {
            const int col = wn * 16 + n2 * 8 + 2 * (lane & 3);
            *(float2*)(out + (size_t)t0 * EMB + h * HDIM + col) =
                make_float2(accO[mt][n2][0] * inv0, accO[mt][n2][1] * inv0);
            *(float2*)(out + (size_t)(t0 + 8) * EMB + h * HDIM + col) =
                make_float2(accO[mt][n2][2] * inv1, accO[mt][n2][3] * inv1);
        }
    }
}

// ---------------------------------------------------------------------------
// fp32 GEMM (only for the 128x128 normal-equations matrix)
// ---------------------------------------------------------------------------
__global__ void __launch_bounds__(256) gemm_f32_kernel(
    const float* __restrict__ A, const float* __restrict__ B,
    float* __restrict__ C, int M, int N, int K)
{
    __shared__ float As[32][132];
    __shared__ float Bs[32][132];

    const int bm = blockIdx.y * 128;
    const int bn = blockIdx.x * 128;
    const int tid = threadIdx.x;
    const int tm = (tid >> 4) << 3;
    const int tn = (tid & 15) << 3;

    float acc[8][8];
#pragma unroll
    for (int i = 0; i < 8; i++)
#pragma unroll
        for (int j = 0; j < 8; j++) acc[i][j] = 0.f;

    for (int k0 = 0; k0 < K; k0 += 32) {
#pragma unroll
        for (int i = 0; i < 4; i++) {
            int idx = tid + i * 256;
            int row = idx >> 3;
            int col = (idx & 7) << 2;
            float4 a = *(const float4*)(A + (size_t)(bm + row) * K + k0 + col);
            As[col + 0][row] = a.x; As[col + 1][row] = a.y;
            As[col + 2][row] = a.z; As[col + 3][row] = a.w;
            float4 b = *(const float4*)(B + (size_t)(bn + row) * K + k0 + col);
            Bs[col + 0][row] = b.x; Bs[col + 1][row] = b.y;
            Bs[col + 2][row] = b.z; Bs[col + 3][row] = b.w;
        }
        __syncthreads();
#pragma unroll
        for (int kk = 0; kk < 32; kk++) {
            float av[8], bv[8];
#pragma unroll
            for (int i = 0; i < 8; i++) { av[i] = As[kk][tm + i]; bv[i] = Bs[kk][tn + i]; }
#pragma unroll
            for (int i = 0; i < 8; i++)
#pragma unroll
                for (int j = 0; j < 8; j++)
                    acc[i][j] += av[i] * bv[j];
        }
        __syncthreads();
    }
#pragma unroll
    for (int i = 0; i < 8; i++)
#pragma unroll
        for (int j = 0; j < 8; j++)
            C[(size_t)(bm + tm + i) * N + bn + tn + j] = acc[i][j];
}

// ---------------------------------------------------------------------------
// Gauss-Jordan inverse of SPD 128x128 g_M -> right half of g_aug
// ---------------------------------------------------------------------------
__global__ void __launch_bounds__(256) gj_kernel()
{
    const int tid = threadIdx.x;
    for (int idx = tid; idx < ODIM * 2 * ODIM; idx += 256) {
        int r = idx >> 8, c = idx & 255;
        g_aug[idx] = (c < ODIM) ? g_M[r * ODIM + c] : ((c - ODIM) == r ? 1.f : 0.f);
    }
    __syncthreads();

    const int r = tid >> 1;
    const int cb = (tid & 1) << 7;
    for (int k = 0; k < ODIM; k++) {
        float ip = 1.f / g_aug[k * 256 + k];
        __syncthreads();
        g_aug[k * 256 + tid] *= ip;
        __syncthreads();
        float f = (r != k) ? g_aug[r * 256 + k] : 0.f;
        __syncthreads();
        const float* prow = &g_aug[k * 256 + cb];
        float* rrow = &g_aug[r * 256 + cb];
#pragma unroll 8
        for (int c = 0; c < 128; c++) rrow[c] -= f * prow[c];
        __syncthreads();
    }
}

// P[o][e] = sum_j Minv[o][j] * W_obs[j][e]
__global__ void __launch_bounds__(256) pmat_kernel(const float* __restrict__ W)
{
    const int o = blockIdx.y;
    const int e = blockIdx.x * 256 + threadIdx.x;
    __shared__ float smv[ODIM];
    if (threadIdx.x < ODIM) smv[threadIdx.x] = g_aug[o * 256 + ODIM + threadIdx.x];
    __syncthreads();
    float acc = 0.f;
#pragma unroll 8
    for (int j = 0; j < ODIM; j++) acc += smv[j] * W[(size_t)j * EMB + e];
    g_P[(size_t)o * EMB + e] = acc;
}

// z[t][e] = sum_o x[t][o] * P[o][e] + PE(s,e)
__global__ void __launch_bounds__(256) embed_kernel(const float* __restrict__ x)
{
    const int t = blockIdx.x;
    const int s = t & (SEQ - 1);
    __shared__ float sx[ODIM];
    if (threadIdx.x < ODIM) sx[threadIdx.x] = x[(size_t)t * ODIM + threadIdx.x];
    __syncthreads();
    float acc[4] = {0.f, 0.f, 0.f, 0.f};
#pragma unroll 4
    for (int o = 0; o < ODIM; o++) {
        float xv = sx[o];
        const float* pr = g_P + (size_t)o * EMB + threadIdx.x;
#pragma unroll
        for (int c = 0; c < 4; c++) acc[c] += xv * pr[c * 256];
    }
    const float kln = 9.210340371976184f / 1024.0f;
#pragma unroll
    for (int c = 0; c < 4; c++) {
        int e = threadIdx.x + c * 256;
        float freq = expf(-(float)(e & ~1) * kln);
        float arg = (float)s * freq;
        float pe = (e & 1) ? cosf(arg) : sinf(arg);
        g_z[(size_t)t * EMB + e] = acc[c] + pe;
    }
}

// ---------------------------------------------------------------------------
// Fused residual + LayerNorm (in place on z)
// ---------------------------------------------------------------------------
__device__ __forceinline__ float block_sum256(float v, float* sbuf)
{
#pragma unroll
    for (int o = 16; o; o >>= 1) v += __shfl_xor_sync(0xffffffffu, v, o);
    if ((threadIdx.x & 31) == 0) sbuf[threadIdx.x >> 5] = v;
    __syncthreads();
    float tot = 0.f;
#pragma unroll
    for (int i = 0; i < 8; i++) tot += sbuf[i];
    return tot;
}

__global__ void __launch_bounds__(256) ln_kernel(float* __restrict__ z,
                                                 const float* __restrict__ add,
                                                 const float* __restrict__ g,
                                                 const float* __restrict__ b)
{
    __shared__ float red[16];
    const size_t t = blockIdx.x;
    float* zp = z + t * EMB;
    const float* ap = add + t * EMB;

    float v[4];
    float s = 0.f;
#pragma unroll
    for (int i = 0; i < 4; i++) {
        int e = threadIdx.x + i * 256;
        v[i] = zp[e] + ap[e];
        s += v[i];
    }
    float mean = block_sum256(s, red) * (1.f / 1024.f);
    float q = 0.f;
#pragma unroll
    for (int i = 0; i < 4; i++) { float d = v[i] - mean; q += d * d; }
    float var = block_sum256(q, red + 8) * (1.f / 1024.f);
    float rstd = rsqrtf(var + 1e-5f);
#pragma unroll
    for (int i = 0; i < 4; i++) {
        int e = threadIdx.x + i * 256;
        zp[e] = (v[i] - mean) * rstd * g[e] + b[e];
    }
}

// ---------------------------------------------------------------------------
// Launch
// ---------------------------------------------------------------------------
extern "C" void kernel_launch(void* const* d_in, const int* in_sizes, int n_in,
                              void* d_out, int out_size)
{
    const float* x     = (const float*)d_in[0];
    const float* W_obs = (const float*)d_in[1];
    const float* Wqkv  = (const float*)d_in[2];
    const float* Wo    = (const float*)d_in[3];
    const float* bo    = (const float*)d_in[4];
    const float* ln1g  = (const float*)d_in[5];
    const float* ln1b  = (const float*)d_in[6];
    const float* W1    = (const float*)d_in[7];
    const float* b1    = (const float*)d_in[8];
    const float* W2    = (const float*)d_in[9];
    const float* b2    = (const float*)d_in[10];
    const float* ln2g  = (const float*)d_in[11];
    const float* ln2b  = (const float*)d_in[12];
    float* out = (float*)d_out;

    float *z, *qkvb, *attnb, *tmpb, *hidb, *Mb;
    cudaGetSymbolAddress((void**)&z,     g_z);
    cudaGetSymbolAddress((void**)&qkvb,  g_qkv);
    cudaGetSymbolAddress((void**)&attnb, g_attn);
    cudaGetSymbolAddress((void**)&tmpb,  g_tmp);
    cudaGetSymbolAddress((void**)&hidb,  g_hid);
    cudaGetSymbolAddress((void**)&Mb,    g_M);

    cudaFuncSetAttribute(gemm_tc_kernel,
                         cudaFuncAttributeMaxDynamicSharedMemorySize, TC_SMEM);
    cudaFuncSetAttribute(gemm_tc64_kernel,
                         cudaFuncAttributeMaxDynamicSharedMemorySize, TC6_SMEM);
    cudaFuncSetAttribute(attn_mma_kernel,
                         cudaFuncAttributeMaxDynamicSharedMemorySize, ATT_SMEM);

    // --- embed: pinv via normal equations (fp32 for conditioning) ---
    gemm_f32_kernel<<<dim3(1, 1), 256>>>(W_obs, W_obs, Mb, ODIM, ODIM, EMB);
    gj_kernel<<<1, 256>>>();
    pmat_kernel<<<dim3(EMB / 256, ODIM), 256>>>(W_obs);
    embed_kernel<<<NTOK, 256>>>(x);

    for (int l = 0; l < NLAYER; l++) {
        const float* wqkv_l = Wqkv + (size_t)l * E3 * EMB;
        const float* wo_l   = Wo   + (size_t)l * EMB * EMB;
        const float* w1_l   = W1   + (size_t)l * HID * EMB;
        const float* w2_l   = W2   + (size_t)l * EMB * HID;

        // QKV: 48x64 = 3072 CTAs (was 768 -> 13.5% wave waste)
        gemm_tc64_kernel<<<dim3(E3 / 64, NTOK / 64), 256, TC6_SMEM>>>(
            z, wqkv_l, nullptr, qkvb, NTOK, E3, EMB, 0);
        attn_mma_kernel<<<dim3(SEQ / 128, BATCH * NHEAD), 256, ATT_SMEM>>>(qkvb, attnb);
        // proj: 16x64 = 1024 CTAs (was 256)
        gemm_tc64_kernel<<<dim3(EMB / 64, NTOK / 64), 256, TC6_SMEM>>>(
            attnb, wo_l, bo + l * EMB, tmpb, NTOK, EMB, EMB, 1);
        ln_kernel<<<NTOK, 256>>>(z, tmpb, ln1g + l * EMB, ln1b + l * EMB);
        // ffn1: keep proven 128x128 (1024 CTAs, 1.2% waste)
        gemm_tc_kernel<<<dim3(HID / TBN, NTOK / TBM), 256, TC_SMEM>>>(
            z, w1_l, b1 + l * HID, hidb, NTOK, HID, EMB, 2);
        // ffn2: 16x64 = 1024 CTAs (was 256)
        gemm_tc64_kernel<<<dim3(EMB / 64, NTOK / 64), 256, TC6_SMEM>>>(
            hidb, w2_l, b2 + l * EMB, tmpb, NTOK, EMB, HID, 1);
        ln_kernel<<<NTOK, 256>>>(z, tmpb, ln2g + l * EMB, ln2b + l * EMB);
    }

    // --- readout: 2x64 = 128 CTAs (was 32 -> 4.6x more parallel) ---
    gemm_tc64_kernel<<<dim3(ODIM / 64, NTOK / 64), 256, TC6_SMEM>>>(
        z, W_obs, nullptr, out, NTOK, ODIM, EMB, 0);
}

// round 16
// speedup vs baseline: 1.0587x; 1.0587x over previous
#include <cuda_runtime.h>
#include <cuda_bf16.h>
#include <cstdint>
#include <cstddef>

// Problem constants
#define BATCH 8
#define SEQ   512
#define NTOK  4096      // BATCH*SEQ
#define EMB   1024
#define E3    3072
#define NHEAD 16
#define HDIM  64
#define HID   4096
#define ODIM  128
#define NLAYER 8

// ---------------------------------------------------------------------------
// Scratch (device globals; allocation is forbidden)
// ---------------------------------------------------------------------------
__device__ float g_z   [(size_t)NTOK * EMB];   // 16 MB
__device__ float g_attn[(size_t)NTOK * EMB];   // 16 MB
__device__ float g_tmp [(size_t)NTOK * EMB];   // 16 MB
__device__ float g_hid [(size_t)NTOK * HID];   // 64 MB
__device__ float g_part[(size_t)2 * NTOK * E3];// 96 MB: QKV(2) / ffn2(4) partials
__device__ float g_M   [ODIM * ODIM];
__device__ float g_aug [ODIM * 2 * ODIM];
__device__ float g_P   [ODIM * EMB];

// ---------------------------------------------------------------------------
// helpers
// ---------------------------------------------------------------------------
__device__ __forceinline__ void ldmatrix4(uint32_t addr, uint32_t& r0, uint32_t& r1,
                                          uint32_t& r2, uint32_t& r3)
{
    asm volatile("ldmatrix.sync.aligned.m8n8.x4.shared.b16 {%0,%1,%2,%3}, [%4];"
                 : "=r"(r0), "=r"(r1), "=r"(r2), "=r"(r3) : "r"(addr));
}

__device__ __forceinline__ void mma16816(float* c, uint32_t a0, uint32_t a1,
                                         uint32_t a2, uint32_t a3,
                                         uint32_t b0, uint32_t b1)
{
    asm volatile("mma.sync.aligned.m16n8k16.row.col.f32.bf16.bf16.f32 "
                 "{%0,%1,%2,%3},{%4,%5,%6,%7},{%8,%9},{%0,%1,%2,%3};"
                 : "+f"(c[0]), "+f"(c[1]), "+f"(c[2]), "+f"(c[3])
                 : "r"(a0), "r"(a1), "r"(a2), "r"(a3), "r"(b0), "r"(b1));
}

__device__ __forceinline__ void split2(float x, float y, uint32_t& h, uint32_t& l)
{
    __nv_bfloat162 hv = __floats2bfloat162_rn(x, y);
    float rx = x - __bfloat162float(hv.x);
    float ry = y - __bfloat162float(hv.y);
    __nv_bfloat162 lv = __floats2bfloat162_rn(rx, ry);
    h = *reinterpret_cast<uint32_t*>(&hv);
    l = *reinterpret_cast<uint32_t*>(&lv);
}

// ===========================================================================
// Tensor-core GEMM 128x128 (champion recipe) with split-K support.
// C_partial[z] = A[:, z*Keff : (z+1)*Keff] * B[:, same]^T
// ld = full row stride of A and B; Keff = per-slice K; grid.z = #slices.
// op: 0=none, 1=bias, 2=bias+relu  (bias ops only used with grid.z==1)
// ===========================================================================
#define TBM 128
#define TBN 128
#define TBK 32
#define RW  20
#define PLANE (128 * RW)
#define BUFW  (4 * PLANE)
#define TC_SMEM (2 * BUFW * 4)

__global__ void __launch_bounds__(256, 1) gemm_tc_kernel(
    const float* __restrict__ A, const float* __restrict__ B,
    const float* __restrict__ bias, float* __restrict__ C,
    int M, int N, int ld, int Keff, int op)
{
    extern __shared__ uint32_t sm[];
    const uint32_t sbase = (uint32_t)__cvta_generic_to_shared(sm);

    const int tid = threadIdx.x;
    const int lane = tid & 31;
    const int wid = tid >> 5;
    const int wm = wid >> 2;
    const int wn = wid & 3;
    const int bm = blockIdx.y * TBM;
    const int bn = blockIdx.x * TBN;
    const int koff = blockIdx.z * Keff;

    float acc[4][4][4];
#pragma unroll
    for (int i = 0; i < 4; i++)
#pragma unroll
        for (int j = 0; j < 4; j++)
#pragma unroll
            for (int r = 0; r < 4; r++) acc[i][j][r] = 0.f;

    int rows[4], c4s[4];
#pragma unroll
    for (int i = 0; i < 4; i++) {
        int f = tid + i * 256;
        rows[i] = f >> 3;
        c4s[i] = (f & 7) << 2;
    }

    const float* Ab = A + (size_t)bm * ld + koff;
    const float* Bb = B + (size_t)bn * ld + koff;
    C += (size_t)blockIdx.z * M * N;

    float4 ra[4], rb[4];

#pragma unroll
    for (int i = 0; i < 4; i++) {
        ra[i] = *(const float4*)(Ab + (size_t)rows[i] * ld + c4s[i]);
        rb[i] = *(const float4*)(Bb + (size_t)rows[i] * ld + c4s[i]);
    }
    {
        uint32_t* buf = sm;
#pragma unroll
        for (int i = 0; i < 4; i++) {
            uint32_t h0, h1, l0, l1;
            int off = rows[i] * RW + (c4s[i] >> 1);
            split2(ra[i].x, ra[i].y, h0, l0);
            split2(ra[i].z, ra[i].w, h1, l1);
            buf[0 * PLANE + off] = h0; buf[0 * PLANE + off + 1] = h1;
            buf[1 * PLANE + off] = l0; buf[1 * PLANE + off + 1] = l1;
            split2(rb[i].x, rb[i].y, h0, l0);
            split2(rb[i].z, rb[i].w, h1, l1);
            buf[2 * PLANE + off] = h0; buf[2 * PLANE + off + 1] = h1;
            buf[3 * PLANE + off] = l0; buf[3 * PLANE + off + 1] = l1;
        }
    }
    __syncthreads();

    const int arow = wm * 64 + (lane & 7) + ((lane & 8) ? 8 : 0);
    const int akw0 = (lane & 16) ? 4 : 0;
    const int brow = wn * 32 + (lane & 7) + ((lane & 16) ? 8 : 0);
    const int bkw0 = (lane & 8) ? 4 : 0;

    const int T = Keff / TBK;
    for (int t = 0; t < T; t++) {
        if (t + 1 < T) {
            const int k0 = (t + 1) * TBK;
#pragma unroll
            for (int i = 0; i < 4; i++) {
                ra[i] = *(const float4*)(Ab + (size_t)rows[i] * ld + k0 + c4s[i]);
                rb[i] = *(const float4*)(Bb + (size_t)rows[i] * ld + k0 + c4s[i]);
            }
        }

        const uint32_t bufb = sbase + (uint32_t)((t & 1) * BUFW) * 4u;
#pragma unroll
        for (int ks = 0; ks < 2; ks++) {
            uint32_t ah[4][4], al[4][4], bh[4][2], bl[4][2];
            const int akw = ks * 8 + akw0;
            const int bkw = ks * 8 + bkw0;
#pragma unroll
            for (int mt = 0; mt < 4; mt++) {
                ldmatrix4(bufb + 4u * (0 * PLANE + (arow + mt * 16) * RW + akw),
                          ah[mt][0], ah[mt][1], ah[mt][2], ah[mt][3]);
                ldmatrix4(bufb + 4u * (1 * PLANE + (arow + mt * 16) * RW + akw),
                          al[mt][0], al[mt][1], al[mt][2], al[mt][3]);
            }
#pragma unroll
            for (int np = 0; np < 2; np++) {
                uint32_t r0, r1, r2, r3;
                ldmatrix4(bufb + 4u * (2 * PLANE + (brow + np * 16) * RW + bkw),
                          r0, r1, r2, r3);
                bh[2 * np][0] = r0; bh[2 * np][1] = r1;
                bh[2 * np + 1][0] = r2; bh[2 * np + 1][1] = r3;
                ldmatrix4(bufb + 4u * (3 * PLANE + (brow + np * 16) * RW + bkw),
                          r0, r1, r2, r3);
                bl[2 * np][0] = r0; bl[2 * np][1] = r1;
                bl[2 * np + 1][0] = r2; bl[2 * np + 1][1] = r3;
            }
#pragma unroll
            for (int mt = 0; mt < 4; mt++)
#pragma unroll
                for (int nt = 0; nt < 4; nt++) {
                    float* c = acc[mt][nt];
                    mma16816(c, ah[mt][0], ah[mt][1], ah[mt][2], ah[mt][3],
                             bh[nt][0], bh[nt][1]);
                    mma16816(c, ah[mt][0], ah[mt][1], ah[mt][2], ah[mt][3],
                             bl[nt][0], bl[nt][1]);
                    mma16816(c, al[mt][0], al[mt][1], al[mt][2], al[mt][3],
                             bh[nt][0], bh[nt][1]);
                }
        }
        __syncthreads();

        if (t + 1 < T) {
            uint32_t* buf = sm + ((t + 1) & 1) * BUFW;
#pragma unroll
            for (int i = 0; i < 4; i++) {
                uint32_t h0, h1, l0, l1;
                int off = rows[i] * RW + (c4s[i] >> 1);
                split2(ra[i].x, ra[i].y, h0, l0);
                split2(ra[i].z, ra[i].w, h1, l1);
                buf[0 * PLANE + off] = h0; buf[0 * PLANE + off + 1] = h1;
                buf[1 * PLANE + off] = l0; buf[1 * PLANE + off + 1] = l1;
                split2(rb[i].x, rb[i].y, h0, l0);
                split2(rb[i].z, rb[i].w, h1, l1);
                buf[2 * PLANE + off] = h0; buf[2 * PLANE + off + 1] = h1;
                buf[3 * PLANE + off] = l0; buf[3 * PLANE + off + 1] = l1;
            }
        }
        __syncthreads();
    }

#pragma unroll
    for (int mt = 0; mt < 4; mt++) {
        const int row = bm + wm * 64 + mt * 16 + (lane >> 2);
#pragma unroll
        for (int nt = 0; nt < 4; nt++) {
            const int col = bn + wn * 32 + nt * 8 + 2 * (lane & 3);
            float b0 = 0.f, b1 = 0.f;
            if (op >= 1) { b0 = bias[col]; b1 = bias[col + 1]; }
            float v0 = acc[mt][nt][0] + b0;
            float v1 = acc[mt][nt][1] + b1;
            float v2 = acc[mt][nt][2] + b0;
            float v3 = acc[mt][nt][3] + b1;
            if (op == 2) {
                v0 = fmaxf(v0, 0.f); v1 = fmaxf(v1, 0.f);
                v2 = fmaxf(v2, 0.f); v3 = fmaxf(v3, 0.f);
            }
            *(float2*)(C + (size_t)row * N + col) = make_float2(v0, v1);
            *(float2*)(C + (size_t)(row + 8) * N + col) = make_float2(v2, v3);
        }
    }
}

// ===========================================================================
// Tensor-core flash attention (champion) reading SUM of two QKV partials.
// grid(4, B*H), 256 threads.
// ===========================================================================
#define RWQ 36
#define RWP 68
#define AQH 0
#define AQL 4608
#define AKH 9216
#define AKL 13824
#define AVH 18432
#define AVL 22784
#define APH 27136
#define APL 35840
#define AWMAX 44544
#define AWSUM 45056
#define ATT_SMEM (45568 * 4)

__global__ void __launch_bounds__(256, 1) attn_mma_kernel(
    const float* __restrict__ qkv0, const float* __restrict__ qkv1,
    float* __restrict__ out)
{
    extern __shared__ uint32_t sm[];
    const uint32_t sbase = (uint32_t)__cvta_generic_to_shared(sm);
    __nv_bfloat16* smh = (__nv_bfloat16*)sm;

    const int tid = threadIdx.x;
    const int lane = tid & 31;
    const int wid = tid >> 5;
    const int wm = wid >> 2, wn = wid & 3;
    const int qg = blockIdx.x;
    const int b = blockIdx.y >> 4, h = blockIdx.y & 15;

    const size_t hoff = (size_t)(b * SEQ) * E3 + h * (3 * HDIM);
    const float* base0 = qkv0 + hoff;
    const float* base1 = qkv1 + hoff;

#pragma unroll
    for (int i = 0; i < 8; i++) {
        int f = tid + i * 256;
        int row = f >> 4, c4 = (f & 15) << 2;
        size_t off_g = (size_t)(qg * 128 + row) * E3 + c4;
        float4 va = *(const float4*)(base0 + off_g);
        float4 vb = *(const float4*)(base1 + off_g);
        float4 v = make_float4(va.x + vb.x, va.y + vb.y, va.z + vb.z, va.w + vb.w);
        uint32_t h0, l0, h1, l1;
        split2(v.x, v.y, h0, l0);
        split2(v.z, v.w, h1, l1);
        int off = row * RWQ + (c4 >> 1);
        sm[AQH + off] = h0; sm[AQH + off + 1] = h1;
        sm[AQL + off] = l0; sm[AQL + off + 1] = l1;
    }

    float accO[4][2][4];
    float m_reg[4][2], l_reg[4][2];
#pragma unroll
    for (int mt = 0; mt < 4; mt++) {
#pragma unroll
        for (int n2 = 0; n2 < 2; n2++)
#pragma unroll
            for (int r = 0; r < 4; r++) accO[mt][n2][r] = 0.f;
        m_reg[mt][0] = -1e30f; m_reg[mt][1] = -1e30f;
        l_reg[mt][0] = 0.f;    l_reg[mt][1] = 0.f;
    }

    const int arow = wm * 64 + (lane & 7) + ((lane & 8) ? 8 : 0);
    const int akw0 = (lane & 16) ? 4 : 0;
    const int brow = wn * 32 + (lane & 7) + ((lane & 16) ? 8 : 0);
    const int bkw0 = (lane & 8) ? 4 : 0;
    const int brow2 = wn * 16 + (lane & 7) + ((lane & 16) ? 8 : 0);
    const int rbase0 = wm * 64 + (lane >> 2);

    float* wmaxf = (float*)&sm[AWMAX];
    float* wsumf = (float*)&sm[AWSUM];

    for (int c = 0; c < 4; c++) {
        __syncthreads();

#pragma unroll
        for (int i = 0; i < 8; i++) {
            int f = tid + i * 256;
            int row = f >> 4, c4 = (f & 15) << 2;
            size_t off_g = (size_t)(c * 128 + row) * E3 + HDIM + c4;
            float4 va = *(const float4*)(base0 + off_g);
            float4 vb = *(const float4*)(base1 + off_g);
            float4 v = make_float4(va.x + vb.x, va.y + vb.y, va.z + vb.z, va.w + vb.w);
            uint32_t h0, l0, h1, l1;
            split2(v.x, v.y, h0, l0);
            split2(v.z, v.w, h1, l1);
            int off = row * RWQ + (c4 >> 1);
            sm[AKH + off] = h0; sm[AKH + off + 1] = h1;
            sm[AKL + off] = l0; sm[AKL + off + 1] = l1;
        }
#pragma unroll
        for (int i = 0; i < 8; i++) {
            int f = tid + i * 256;
            int r = f >> 4, d4 = (f & 15) << 2;
            size_t off_g = (size_t)(c * 128 + r) * E3 + 2 * HDIM + d4;
            float4 va = *(const float4*)(base0 + off_g);
            float4 vb = *(const float4*)(base1 + off_g);
            float vv[4] = {va.x + vb.x, va.y + vb.y, va.z + vb.z, va.w + vb.w};
#pragma unroll
            for (int j = 0; j < 4; j++) {
                __nv_bfloat16 hb = __float2bfloat16_rn(vv[j]);
                __nv_bfloat16 lb = __float2bfloat16_rn(vv[j] - __bfloat162float(hb));
                smh[(AVH + (d4 + j) * RWP) * 2 + r] = hb;
                smh[(AVL + (d4 + j) * RWP) * 2 + r] = lb;
            }
        }
        __syncthreads();

        float accS[4][4][4];
#pragma unroll
        for (int i = 0; i < 4; i++)
#pragma unroll
            for (int j = 0; j < 4; j++)
#pragma unroll
                for (int r = 0; r < 4; r++) accS[i][j][r] = 0.f;

#pragma unroll
        for (int kt = 0; kt < 2; kt++)
#pragma unroll
            for (int ks = 0; ks < 2; ks++) {
                const int akw = kt * 16 + ks * 8 + akw0;
                const int bkw = kt * 16 + ks * 8 + bkw0;
                uint32_t qh[4][4], ql[4][4], kh[4][2], kl[4][2];
#pragma unroll
                for (int mt = 0; mt < 4; mt++) {
                    ldmatrix4(sbase + 4u * (AQH + (arow + mt * 16) * RWQ + akw),
                              qh[mt][0], qh[mt][1], qh[mt][2], qh[mt][3]);
                    ldmatrix4(sbase + 4u * (AQL + (arow + mt * 16) * RWQ + akw),
                              ql[mt][0], ql[mt][1], ql[mt][2], ql[mt][3]);
                }
#pragma unroll
                for (int np = 0; np < 2; np++) {
                    uint32_t r0, r1, r2, r3;
                    ldmatrix4(sbase + 4u * (AKH + (brow + np * 16) * RWQ + bkw),
                              r0, r1, r2, r3);
                    kh[2 * np][0] = r0; kh[2 * np][1] = r1;
                    kh[2 * np + 1][0] = r2; kh[2 * np + 1][1] = r3;
                    ldmatrix4(sbase + 4u * (AKL + (brow + np * 16) * RWQ + bkw),
                              r0, r1, r2, r3);
                    kl[2 * np][0] = r0; kl[2 * np][1] = r1;
                    kl[2 * np + 1][0] = r2; kl[2 * np + 1][1] = r3;
                }
#pragma unroll
                for (int mt = 0; mt < 4; mt++)
#pragma unroll
                    for (int nt = 0; nt < 4; nt++) {
                        float* cc = accS[mt][nt];
                        mma16816(cc, qh[mt][0], qh[mt][1], qh[mt][2], qh[mt][3],
                                 kh[nt][0], kh[nt][1]);
                        mma16816(cc, qh[mt][0], qh[mt][1], qh[mt][2], qh[mt][3],
                                 kl[nt][0], kl[nt][1]);
                        mma16816(cc, ql[mt][0], ql[mt][1], ql[mt][2], ql[mt][3],
                                 kh[nt][0], kh[nt][1]);
                    }
            }

#pragma unroll
        for (int mt = 0; mt < 4; mt++) {
            float x0 = accS[mt][0][0], x1 = accS[mt][0][2];
#pragma unroll
            for (int nt = 0; nt < 4; nt++) {
                x0 = fmaxf(x0, fmaxf(accS[mt][nt][0], accS[mt][nt][1]));
                x1 = fmaxf(x1, fmaxf(accS[mt][nt][2], accS[mt][nt][3]));
            }
            x0 = fmaxf(x0, __shfl_xor_sync(0xffffffffu, x0, 1));
            x0 = fmaxf(x0, __shfl_xor_sync(0xffffffffu, x0, 2));
            x1 = fmaxf(x1, __shfl_xor_sync(0xffffffffu, x1, 1));
            x1 = fmaxf(x1, __shfl_xor_sync(0xffffffffu, x1, 2));
            if ((lane & 3) == 0) {
                wmaxf[wn * 128 + rbase0 + mt * 16] = x0;
                wmaxf[wn * 128 + rbase0 + mt * 16 + 8] = x1;
            }
        }
        __syncthreads();

        float alpha[4][2], psum[4][2];
#pragma unroll
        for (int mt = 0; mt < 4; mt++)
#pragma unroll
            for (int j = 0; j < 2; j++) {
                int row = rbase0 + mt * 16 + j * 8;
                float mc = fmaxf(fmaxf(wmaxf[row], wmaxf[128 + row]),
                                 fmaxf(wmaxf[256 + row], wmaxf[384 + row])) * 0.125f;
                float mn = fmaxf(m_reg[mt][j], mc);
                alpha[mt][j] = __expf(m_reg[mt][j] - mn);
                m_reg[mt][j] = mn;
                psum[mt][j] = 0.f;
            }
#pragma unroll
        for (int mt = 0; mt < 4; mt++) {
            const int row = rbase0 + mt * 16;
#pragma unroll
            for (int nt = 0; nt < 4; nt++) {
                const int col = wn * 32 + nt * 8 + 2 * (lane & 3);
                float p0 = __expf(accS[mt][nt][0] * 0.125f - m_reg[mt][0]);
                float p1 = __expf(accS[mt][nt][1] * 0.125f - m_reg[mt][0]);
                float p2 = __expf(accS[mt][nt][2] * 0.125f - m_reg[mt][1]);
                float p3 = __expf(accS[mt][nt][3] * 0.125f - m_reg[mt][1]);
                psum[mt][0] += p0 + p1;
                psum[mt][1] += p2 + p3;
                uint32_t hh, ll;
                split2(p0, p1, hh, ll);
                sm[APH + row * RWP + (col >> 1)] = hh;
                sm[APL + row * RWP + (col >> 1)] = ll;
                split2(p2, p3, hh, ll);
                sm[APH + (row + 8) * RWP + (col >> 1)] = hh;
                sm[APL + (row + 8) * RWP + (col >> 1)] = ll;
            }
        }
#pragma unroll
        for (int mt = 0; mt < 4; mt++)
#pragma unroll
            for (int j = 0; j < 2; j++) {
                float s = psum[mt][j];
                s += __shfl_xor_sync(0xffffffffu, s, 1);
                s += __shfl_xor_sync(0xffffffffu, s, 2);
                psum[mt][j] = s;
            }
        if ((lane & 3) == 0)
#pragma unroll
            for (int mt = 0; mt < 4; mt++) {
                wsumf[wn * 128 + rbase0 + mt * 16] = psum[mt][0];
                wsumf[wn * 128 + rbase0 + mt * 16 + 8] = psum[mt][1];
            }
#pragma unroll
        for (int mt = 0; mt < 4; mt++)
#pragma unroll
            for (int n2 = 0; n2 < 2; n2++) {
                accO[mt][n2][0] *= alpha[mt][0];
                accO[mt][n2][1] *= alpha[mt][0];
                accO[mt][n2][2] *= alpha[mt][1];
                accO[mt][n2][3] *= alpha[mt][1];
            }
        __syncthreads();

#pragma unroll
        for (int mt = 0; mt < 4; mt++)
#pragma unroll
            for (int j = 0; j < 2; j++) {
                int row = rbase0 + mt * 16 + j * 8;
                float s = wsumf[row] + wsumf[128 + row] + wsumf[256 + row] + wsumf[384 + row];
                l_reg[mt][j] = l_reg[mt][j] * alpha[mt][j] + s;
            }

#pragma unroll
        for (int kt = 0; kt < 4; kt++)
#pragma unroll
            for (int ks = 0; ks < 2; ks++) {
                const int akw = kt * 16 + ks * 8 + akw0;
                const int bkw = kt * 16 + ks * 8 + bkw0;
                uint32_t ph[4][4], pl[4][4], vh[2][2], vl[2][2];
#pragma unroll
                for (int mt = 0; mt < 4; mt++) {
                    ldmatrix4(sbase + 4u * (APH + (arow + mt * 16) * RWP + akw),
                              ph[mt][0], ph[mt][1], ph[mt][2], ph[mt][3]);
                    ldmatrix4(sbase + 4u * (APL + (arow + mt * 16) * RWP + akw),
                              pl[mt][0], pl[mt][1], pl[mt][2], pl[mt][3]);
                }
                {
                    uint32_t r0, r1, r2, r3;
                    ldmatrix4(sbase + 4u * (AVH + brow2 * RWP + bkw), r0, r1, r2, r3);
                    vh[0][0] = r0; vh[0][1] = r1; vh[1][0] = r2; vh[1][1] = r3;
                    ldmatrix4(sbase + 4u * (AVL + brow2 * RWP + bkw), r0, r1, r2, r3);
                    vl[0][0] = r0; vl[0][1] = r1; vl[1][0] = r2; vl[1][1] = r3;
                }
#pragma unroll
                for (int mt = 0; mt < 4; mt++)
#pragma unroll
                    for (int n2 = 0; n2 < 2; n2++) {
                        float* cc = accO[mt][n2];
                        mma16816(cc, ph[mt][0], ph[mt][1], ph[mt][2], ph[mt][3],
                                 vh[n2][0], vh[n2][1]);
                        mma16816(cc, ph[mt][0], ph[mt][1], ph[mt][2], ph[mt][3],
                                 vl[n2][0], vl[n2][1]);
                        mma16816(cc, pl[mt][0], pl[mt][1], pl[mt][2], pl[mt][3],
                                 vh[n2][0], vh[n2][1]);
                    }
            }
    }

#pragma unroll
    for (int mt = 0; mt < 4; mt++) {
        const int row = rbase0 + mt * 16;
        const int t0 = b * SEQ + qg * 128 + row;
        const float inv0 = 1.f / l_reg[mt][0];
        const float inv1 = 1.f / l_reg[mt][1];
#pragma unroll
        for (int n2 = 0; n2 < 2; n2++) {
            const int col = wn * 16 + n2 * 8 + 2 * (lane & 3);
            *(float2*)(out + (size_t)t0 * EMB + h * HDIM + col) =
                make_float2(accO[mt][n2][0] * inv0, accO[mt][n2][1] * inv0);
            *(float2*)(out + (size_t)(t0 + 8) * EMB + h * HDIM + col) =
                make_float2(accO[mt][n2][2] * inv1, accO[mt][n2][3] * inv1);
        }
    }
}

// ---------------------------------------------------------------------------
// fp32 GEMM (only for the 128x128 normal-equations matrix)
// ---------------------------------------------------------------------------
__global__ void __launch_bounds__(256) gemm_f32_kernel(
    const float* __restrict__ A, const float* __restrict__ B,
    float* __restrict__ C, int M, int N, int K)
{
    __shared__ float As[32][132];
    __shared__ float Bs[32][132];

    const int bm = blockIdx.y * 128;
    const int bn = blockIdx.x * 128;
    const int tid = threadIdx.x;
    const int tm = (tid >> 4) << 3;
    const int tn = (tid & 15) << 3;

    float acc[8][8];
#pragma unroll
    for (int i = 0; i < 8; i++)
#pragma unroll
        for (int j = 0; j < 8; j++) acc[i][j] = 0.f;

    for (int k0 = 0; k0 < K; k0 += 32) {
#pragma unroll
        for (int i = 0; i < 4; i++) {
            int idx = tid + i * 256;
            int row = idx >> 3;
            int col = (idx & 7) << 2;
            float4 a = *(const float4*)(A + (size_t)(bm + row) * K + k0 + col);
            As[col + 0][row] = a.x; As[col + 1][row] = a.y;
            As[col + 2][row] = a.z; As[col + 3][row] = a.w;
            float4 b = *(const float4*)(B + (size_t)(bn + row) * K + k0 + col);
            Bs[col + 0][row] = b.x; Bs[col + 1][row] = b.y;
            Bs[col + 2][row] = b.z; Bs[col + 3][row] = b.w;
        }
        __syncthreads();
#pragma unroll
        for (int kk = 0; kk < 32; kk++) {
            float av[8], bv[8];
#pragma unroll
            for (int i = 0; i < 8; i++) { av[i] = As[kk][tm + i]; bv[i] = Bs[kk][tn + i]; }
#pragma unroll
            for (int i = 0; i < 8; i++)
#pragma unroll
                for (int j = 0; j < 8; j++)
                    acc[i][j] += av[i] * bv[j];
        }
        __syncthreads();
    }
#pragma unroll
    for (int i = 0; i < 8; i++)
#pragma unroll
        for (int j = 0; j < 8; j++)
            C[(size_t)(bm + tm + i) * N + bn + tn + j] = acc[i][j];
}

// ---------------------------------------------------------------------------
// Gauss-Jordan inverse of SPD 128x128 g_M -> right half of g_aug
// ---------------------------------------------------------------------------
__global__ void __launch_bounds__(256) gj_kernel()
{
    const int tid = threadIdx.x;
    for (int idx = tid; idx < ODIM * 2 * ODIM; idx += 256) {
        int r = idx >> 8, c = idx & 255;
        g_aug[idx] = (c < ODIM) ? g_M[r * ODIM + c] : ((c - ODIM) == r ? 1.f : 0.f);
    }
    __syncthreads();

    const int r = tid >> 1;
    const int cb = (tid & 1) << 7;
    for (int k = 0; k < ODIM; k++) {
        float ip = 1.f / g_aug[k * 256 + k];
        __syncthreads();
        g_aug[k * 256 + tid] *= ip;
        __syncthreads();
        float f = (r != k) ? g_aug[r * 256 + k] : 0.f;
        __syncthreads();
        const float* prow = &g_aug[k * 256 + cb];
        float* rrow = &g_aug[r * 256 + cb];
#pragma unroll 8
        for (int c = 0; c < 128; c++) rrow[c] -= f * prow[c];
        __syncthreads();
    }
}

// P[o][e] = sum_j Minv[o][j] * W_obs[j][e]
__global__ void __launch_bounds__(256) pmat_kernel(const float* __restrict__ W)
{
    const int o = blockIdx.y;
    const int e = blockIdx.x * 256 + threadIdx.x;
    __shared__ float smv[ODIM];
    if (threadIdx.x < ODIM) smv[threadIdx.x] = g_aug[o * 256 + ODIM + threadIdx.x];
    __syncthreads();
    float acc = 0.f;
#pragma unroll 8
    for (int j = 0; j < ODIM; j++) acc += smv[j] * W[(size_t)j * EMB + e];
    g_P[(size_t)o * EMB + e] = acc;
}

// z[t][e] = sum_o x[t][o] * P[o][e] + PE(s,e)
__global__ void __launch_bounds__(256) embed_kernel(const float* __restrict__ x)
{
    const int t = blockIdx.x;
    const int s = t & (SEQ - 1);
    __shared__ float sx[ODIM];
    if (threadIdx.x < ODIM) sx[threadIdx.x] = x[(size_t)t * ODIM + threadIdx.x];
    __syncthreads();
    float acc[4] = {0.f, 0.f, 0.f, 0.f};
#pragma unroll 4
    for (int o = 0; o < ODIM; o++) {
        float xv = sx[o];
        const float* pr = g_P + (size_t)o * EMB + threadIdx.x;
#pragma unroll
        for (int c = 0; c < 4; c++) acc[c] += xv * pr[c * 256];
    }
    const float kln = 9.210340371976184f / 1024.0f;
#pragma unroll
    for (int c = 0; c < 4; c++) {
        int e = threadIdx.x + c * 256;
        float freq = expf(-(float)(e & ~1) * kln);
        float arg = (float)s * freq;
        float pe = (e & 1) ? cosf(arg) : sinf(arg);
        g_z[(size_t)t * EMB + e] = acc[c] + pe;
    }
}

// ---------------------------------------------------------------------------
// Fused residual + LayerNorm (in place on z); add = single buffer
// ---------------------------------------------------------------------------
__device__ __forceinline__ float block_sum256(float v, float* sbuf)
{
#pragma unroll
    for (int o = 16; o; o >>= 1) v += __shfl_xor_sync(0xffffffffu, v, o);
    if ((threadIdx.x & 31) == 0) sbuf[threadIdx.x >> 5] = v;
    __syncthreads();
    float tot = 0.f;
#pragma unroll
    for (int i = 0; i < 8; i++) tot += sbuf[i];
    return tot;
}

__global__ void __launch_bounds__(256) ln_kernel(float* __restrict__ z,
                                                 const float* __restrict__ add,
                                                 const float* __restrict__ g,
                                                 const float* __restrict__ b)
{
    __shared__ float red[16];
    const size_t t = blockIdx.x;
    float* zp = z + t * EMB;
    const float* ap = add + t * EMB;

    float v[4];
    float s = 0.f;
#pragma unroll
    for (int i = 0; i < 4; i++) {
        int e = threadIdx.x + i * 256;
        v[i] = zp[e] + ap[e];
        s += v[i];
    }
    float mean = block_sum256(s, red) * (1.f / 1024.f);
    float q = 0.f;
#pragma unroll
    for (int i = 0; i < 4; i++) { float d = v[i] - mean; q += d * d; }
    float var = block_sum256(q, red + 8) * (1.f / 1024.f);
    float rstd = rsqrtf(var + 1e-5f);
#pragma unroll
    for (int i = 0; i < 4; i++) {
        int e = threadIdx.x + i * 256;
        zp[e] = (v[i] - mean) * rstd * g[e] + b[e];
    }
}

// ---------------------------------------------------------------------------
// Fused 4-partial sum + bias + residual + LayerNorm (for split-K ffn2)
// add = g_part base; partials at stride NTOK*EMB.
// ---------------------------------------------------------------------------
__global__ void __launch_bounds__(256) ln_sum4_kernel(float* __restrict__ z,
                                                      const float* __restrict__ parts,
                                                      const float* __restrict__ bias,
                                                      const float* __restrict__ g,
                                                      const float* __restrict__ b)
{
    __shared__ float red[16];
    const size_t t = blockIdx.x;
    const size_t PS = (size_t)NTOK * EMB;
    float* zp = z + t * EMB;
    const float* p0 = parts + t * EMB;

    float v[4];
    float s = 0.f;
#pragma unroll
    for (int i = 0; i < 4; i++) {
        int e = threadIdx.x + i * 256;
        float sum = p0[e] + p0[PS + e] + p0[2 * PS + e] + p0[3 * PS + e] + bias[e];
        v[i] = zp[e] + sum;
        s += v[i];
    }
    float mean = block_sum256(s, red) * (1.f / 1024.f);
    float q = 0.f;
#pragma unroll
    for (int i = 0; i < 4; i++) { float d = v[i] - mean; q += d * d; }
    float var = block_sum256(q, red + 8) * (1.f / 1024.f);
    float rstd = rsqrtf(var + 1e-5f);
#pragma unroll
    for (int i = 0; i < 4; i++) {
        int e = threadIdx.x + i * 256;
        zp[e] = (v[i] - mean) * rstd * g[e] + b[e];
    }
}

// ---------------------------------------------------------------------------
// Launch
// ---------------------------------------------------------------------------
extern "C" void kernel_launch(void* const* d_in, const int* in_sizes, int n_in,
                              void* d_out, int out_size)
{
    const float* x     = (const float*)d_in[0];
    const float* W_obs = (const float*)d_in[1];
    const float* Wqkv  = (const float*)d_in[2];
    const float* Wo    = (const float*)d_in[3];
    const float* bo    = (const float*)d_in[4];
    const float* ln1g  = (const float*)d_in[5];
    const float* ln1b  = (const float*)d_in[6];
    const float* W1    = (const float*)d_in[7];
    const float* b1    = (const float*)d_in[8];
    const float* W2    = (const float*)d_in[9];
    const float* b2    = (const float*)d_in[10];
    const float* ln2g  = (const float*)d_in[11];
    const float* ln2b  = (const float*)d_in[12];
    float* out = (float*)d_out;

    float *z, *attnb, *tmpb, *hidb, *partb, *Mb;
    cudaGetSymbolAddress((void**)&z,     g_z);
    cudaGetSymbolAddress((void**)&attnb, g_attn);
    cudaGetSymbolAddress((void**)&tmpb,  g_tmp);
    cudaGetSymbolAddress((void**)&hidb,  g_hid);
    cudaGetSymbolAddress((void**)&partb, g_part);
    cudaGetSymbolAddress((void**)&Mb,    g_M);

    cudaFuncSetAttribute(gemm_tc_kernel,
                         cudaFuncAttributeMaxDynamicSharedMemorySize, TC_SMEM);
    cudaFuncSetAttribute(attn_mma_kernel,
                         cudaFuncAttributeMaxDynamicSharedMemorySize, ATT_SMEM);

    // --- embed: pinv via normal equations (fp32 for conditioning) ---
    gemm_f32_kernel<<<dim3(1, 1), 256>>>(W_obs, W_obs, Mb, ODIM, ODIM, EMB);
    gj_kernel<<<1, 256>>>();
    pmat_kernel<<<dim3(EMB / 256, ODIM), 256>>>(W_obs);
    embed_kernel<<<NTOK, 256>>>(x);

    const size_t QS = (size_t)NTOK * E3;   // QKV partial stride

    for (int l = 0; l < NLAYER; l++) {
        const float* wqkv_l = Wqkv + (size_t)l * E3 * EMB;
        const float* wo_l   = Wo   + (size_t)l * EMB * EMB;
        const float* w1_l   = W1   + (size_t)l * HID * EMB;
        const float* w2_l   = W2   + (size_t)l * EMB * HID;

        // QKV split-K=2: grid(24,32,2), Keff=512 -> partials in g_part
        gemm_tc_kernel<<<dim3(E3 / TBN, NTOK / TBM, 2), 256, TC_SMEM>>>(
            z, wqkv_l, nullptr, partb, NTOK, E3, EMB, EMB / 2, 0);
        // attention sums the two partials while staging
        attn_mma_kernel<<<dim3(SEQ / 128, BATCH * NHEAD), 256, ATT_SMEM>>>(
            partb, partb + QS, attnb);
        gemm_tc_kernel<<<dim3(EMB / TBN, NTOK / TBM), 256, TC_SMEM>>>(
            attnb, wo_l, bo + l * EMB, tmpb, NTOK, EMB, EMB, EMB, 1);
        ln_kernel<<<NTOK, 256>>>(z, tmpb, ln1g + l * EMB, ln1b + l * EMB);
        gemm_tc_kernel<<<dim3(HID / TBN, NTOK / TBM), 256, TC_SMEM>>>(
            z, w1_l, b1 + l * HID, hidb, NTOK, HID, EMB, EMB, 2);
        // ffn2 split-K=4: grid(8,32,4), Keff=1024 -> partials in g_part
        gemm_tc_kernel<<<dim3(EMB / TBN, NTOK / TBM, 4), 256, TC_SMEM>>>(
            hidb, w2_l, nullptr, partb, NTOK, EMB, HID, HID / 4, 0);
        // LN sums 4 partials + bias + residual
        ln_sum4_kernel<<<NTOK, 256>>>(z, partb, b2 + l * EMB,
                                      ln2g + l * EMB, ln2b + l * EMB);
    }

    // --- readout: x_hat = z @ W_obs^T ---
    gemm_tc_kernel<<<dim3(ODIM / TBN, NTOK / TBM), 256, TC_SMEM>>>(
        z, W_obs, nullptr, out, NTOK, ODIM, EMB, EMB, 0);
}